// round 11
// baseline (speedup 1.0000x reference)
#include <cuda_runtime.h>
#include <cuda_fp16.h>
#include <cstdint>
#include <cstddef>

// Problem constants
#define N_NODES   20000
#define N_EDGES   320000
#define N_GRAPHS  64
#define NODE_DIM  128
#define GLOB_DIM  16
#define HIDDEN    256
#define NUM_LAYERS 4

// Dynamic-range shift for fp16 storage of z/t/hh (exact power of two)
#define H_SCALE   (1.0f / 256.0f)
#define H_UNSCALE 256.0f

// ---------------------------------------------------------------------------
// Scratch (static __device__ allocations)
// ---------------------------------------------------------------------------
__device__ float  g_hA[N_NODES * HIDDEN];
__device__ float  g_hB[N_NODES * HIDDEN];
__device__ __half g_hh[N_NODES * HIDDEN];     // half mirror of h (x2^-8), gather input
__device__ __half g_z [N_NODES * HIDDEN];     // aggregated features (half, x2^-8)
__device__ __half g_t [N_NODES * HIDDEN];     // MLP hidden (half, x2^-8)
__device__ __half g_Wh[8 * HIDDEN * HIDDEN];  // half weights, natural [K][256] layout

__device__ int    g_deg   [N_NODES];
__device__ int    g_rowptr[N_NODES + 1];
__device__ int    g_cursor[N_NODES];
__device__ int    g_col   [N_EDGES];

__device__ float  g_pooled[N_GRAPHS * HIDDEN];
__device__ float  g_cnt   [N_GRAPHS];

// ---------------------------------------------------------------------------
// Helpers
// ---------------------------------------------------------------------------
__device__ __forceinline__ void mma16(float* c, const uint32_t* a, const uint32_t* b) {
    asm volatile(
        "mma.sync.aligned.m16n8k16.row.col.f32.f16.f16.f32 "
        "{%0,%1,%2,%3}, {%4,%5,%6,%7}, {%8,%9}, {%0,%1,%2,%3};"
        : "+f"(c[0]), "+f"(c[1]), "+f"(c[2]), "+f"(c[3])
        : "r"(a[0]), "r"(a[1]), "r"(a[2]), "r"(a[3]), "r"(b[0]), "r"(b[1]));
}

__device__ __forceinline__ void cp16p(void* dst, const void* src, int srcbytes) {
    uint32_t d = (uint32_t)__cvta_generic_to_shared(dst);
    asm volatile("cp.async.cg.shared.global [%0], [%1], 16, %2;"
                 :: "r"(d), "l"(src), "r"(srcbytes));
}
__device__ __forceinline__ void cp16(void* dst, const void* src) {
    uint32_t d = (uint32_t)__cvta_generic_to_shared(dst);
    asm volatile("cp.async.cg.shared.global [%0], [%1], 16;"
                 :: "r"(d), "l"(src));
}
#define CP_COMMIT() asm volatile("cp.async.commit_group;" ::: "memory")

// ---------------------------------------------------------------------------
// CSR build (unchanged)
// ---------------------------------------------------------------------------
__global__ void k_zero() {
    int i = blockIdx.x * blockDim.x + threadIdx.x;
    if (i < N_NODES) g_deg[i] = 0;
    if (i < N_GRAPHS * HIDDEN) g_pooled[i] = 0.f;
    if (i < N_GRAPHS) g_cnt[i] = 0.f;
}

__global__ void k_count(const int* __restrict__ dst) {
    int e = (blockIdx.x * blockDim.x + threadIdx.x) * 4;
#pragma unroll
    for (int j = 0; j < 4; j++)
        if (e + j < N_EDGES) atomicAdd(&g_deg[dst[e + j]], 1);
}

__global__ void k_scan() {
    const int T = 512;
    const int CH = (N_NODES + T - 1) / T;
    __shared__ int part[T];
    int t = threadIdx.x;
    int base = t * CH;
    int s = 0;
    for (int j = 0; j < CH; j++) {
        int i = base + j;
        if (i < N_NODES) s += g_deg[i];
    }
    part[t] = s;
    __syncthreads();
    for (int off = 1; off < T; off <<= 1) {
        int v = (t >= off) ? part[t - off] : 0;
        __syncthreads();
        part[t] += v;
        __syncthreads();
    }
    int run = (t > 0) ? part[t - 1] : 0;
    for (int j = 0; j < CH; j++) {
        int i = base + j;
        if (i < N_NODES) {
            g_rowptr[i] = run;
            g_cursor[i] = run;
            run += g_deg[i];
        }
    }
    if (t == T - 1) g_rowptr[N_NODES] = run;
}

__global__ void k_fill(const int* __restrict__ src, const int* __restrict__ dst) {
    int e = (blockIdx.x * blockDim.x + threadIdx.x) * 4;
#pragma unroll
    for (int j = 0; j < 4; j++) {
        if (e + j < N_EDGES) {
            int d = dst[e + j];
            int p = atomicAdd(&g_cursor[d], 1);
            g_col[p] = src[e + j];
        }
    }
}

// ---------------------------------------------------------------------------
// Weight rounding to half (natural [K][256] layout)
// ---------------------------------------------------------------------------
struct P8 { const float* p[8]; int n[8]; };

__global__ void k_round_all(P8 ps, __half* __restrict__ out) {
    int i = blockIdx.x * blockDim.x + threadIdx.x;
    int slot = i >> 16;
    int off  = i & 65535;
    if (slot < 8 && off < ps.n[slot])
        out[(size_t)slot * 65536 + off] = __float2half_rn(ps.p[slot][off]);
}

// ---------------------------------------------------------------------------
// GIN aggregation, layer 0: fp32 gather from x; store half scaled (x2^-8)
// ---------------------------------------------------------------------------
template <int DIM4>
__global__ void k_aggr(const float* __restrict__ h, __half* __restrict__ z,
                       const float* __restrict__ eps, int layer) {
    const int NPB = 128 / DIM4;
    int v = blockIdx.x * NPB + threadIdx.x / DIM4;
    if (v >= N_NODES) return;
    int t = threadIdx.x % DIM4;
    float ep = 1.0f + eps[layer];
    const float4* h4 = (const float4*)h;
    float4 a = h4[(size_t)v * DIM4 + t];
    float4 acc;
    acc.x = ep * a.x; acc.y = ep * a.y; acc.z = ep * a.z; acc.w = ep * a.w;
    int j = g_rowptr[v], s1 = g_rowptr[v + 1];
    for (; j + 4 <= s1; j += 4) {
        int i0 = g_col[j], i1 = g_col[j + 1], i2 = g_col[j + 2], i3 = g_col[j + 3];
        float4 b0 = h4[(size_t)i0 * DIM4 + t];
        float4 b1 = h4[(size_t)i1 * DIM4 + t];
        float4 b2 = h4[(size_t)i2 * DIM4 + t];
        float4 b3 = h4[(size_t)i3 * DIM4 + t];
        acc.x += (b0.x + b1.x) + (b2.x + b3.x);
        acc.y += (b0.y + b1.y) + (b2.y + b3.y);
        acc.z += (b0.z + b1.z) + (b2.z + b3.z);
        acc.w += (b0.w + b1.w) + (b2.w + b3.w);
    }
    for (; j < s1; ++j) {
        int s = g_col[j];
        float4 b = h4[(size_t)s * DIM4 + t];
        acc.x += b.x; acc.y += b.y; acc.z += b.z; acc.w += b.w;
    }
    __half2 o0 = __floats2half2_rn(acc.x * H_SCALE, acc.y * H_SCALE);
    __half2 o1 = __floats2half2_rn(acc.z * H_SCALE, acc.w * H_SCALE);
    uint2 st;
    st.x = *(uint32_t*)&o0;
    st.y = *(uint32_t*)&o1;
    ((uint2*)z)[(size_t)v * DIM4 + t] = st;
}

// ---------------------------------------------------------------------------
// GIN aggregation, layers 1-3: gather from scaled half hh; fp32 accumulate;
// output already in scaled domain (inputs scaled) -> store half directly.
// DIM8 = HIDDEN/8 = 32 (16B chunks per node). blockDim 128 -> 4 nodes/block.
// ---------------------------------------------------------------------------
template <int DIM8>
__global__ void k_aggr_h(const __half* __restrict__ hh, __half* __restrict__ z,
                         const float* __restrict__ eps, int layer) {
    const int NPB = 128 / DIM8;
    int v = blockIdx.x * NPB + threadIdx.x / DIM8;
    if (v >= N_NODES) return;
    int t = threadIdx.x % DIM8;
    float ep = 1.0f + eps[layer];
    const uint4* h4 = (const uint4*)hh;

    float2 acc[4];
    {
        uint4 a = h4[(size_t)v * DIM8 + t];
        const __half2* ha = (const __half2*)&a;
#pragma unroll
        for (int q = 0; q < 4; q++) {
            float2 f = __half22float2(ha[q]);
            acc[q].x = ep * f.x; acc[q].y = ep * f.y;
        }
    }
    int j = g_rowptr[v], s1 = g_rowptr[v + 1];
    for (; j + 4 <= s1; j += 4) {
        int i0 = g_col[j], i1 = g_col[j + 1], i2 = g_col[j + 2], i3 = g_col[j + 3];
        uint4 b0 = h4[(size_t)i0 * DIM8 + t];
        uint4 b1 = h4[(size_t)i1 * DIM8 + t];
        uint4 b2 = h4[(size_t)i2 * DIM8 + t];
        uint4 b3 = h4[(size_t)i3 * DIM8 + t];
        const __half2* p0 = (const __half2*)&b0;
        const __half2* p1 = (const __half2*)&b1;
        const __half2* p2 = (const __half2*)&b2;
        const __half2* p3 = (const __half2*)&b3;
#pragma unroll
        for (int q = 0; q < 4; q++) {
            float2 f0 = __half22float2(p0[q]), f1 = __half22float2(p1[q]);
            float2 f2 = __half22float2(p2[q]), f3 = __half22float2(p3[q]);
            acc[q].x += (f0.x + f1.x) + (f2.x + f3.x);
            acc[q].y += (f0.y + f1.y) + (f2.y + f3.y);
        }
    }
    for (; j < s1; ++j) {
        uint4 b = h4[(size_t)g_col[j] * DIM8 + t];
        const __half2* pb = (const __half2*)&b;
#pragma unroll
        for (int q = 0; q < 4; q++) {
            float2 f = __half22float2(pb[q]);
            acc[q].x += f.x; acc[q].y += f.y;
        }
    }
    uint4 o;
    __half2* ho = (__half2*)&o;
#pragma unroll
    for (int q = 0; q < 4; q++) ho[q] = __floats2half2_rn(acc[q].x, acc[q].y);
    ((uint4*)z)[(size_t)v * DIM8 + t] = o;
}

// ---------------------------------------------------------------------------
// fp16 tensor-core GEMM: C[n x 256] = epi((A*2^-8)[n x K] @ B[K x 256])
// acc is rescaled by 2^8 before bias. A: half [n][K]. B: half [K][256].
// 128 threads (4 warps), CTA tile 128x128, warp tile 64x64, BK=32,
// 3-stage cp.async ring, 2 CTAs/SM.
// HALFOUT: store half CH (x2^-8). Else: fp32 C (+ residual), and if CH!=null
// also a scaled half mirror (feeds next layer's gather).
// ---------------------------------------------------------------------------
static constexpr int AS_H = 128 * 40;   // halves per A stage ([m][k], pitch 40)
static constexpr int BS_H = 32 * 136;   // halves per B stage ([k][n], pitch 136)
static constexpr int GEMM_SMEM_BYTES = 3 * (AS_H + BS_H) * 2;   // 56832

template <int K, bool RESID, bool HALFOUT>
__global__ __launch_bounds__(128, 2)
void k_gemm(const __half* __restrict__ A, const __half* __restrict__ B,
            const float* __restrict__ bias, const float* __restrict__ R,
            float* __restrict__ C, __half* __restrict__ CH, int n) {
    extern __shared__ __half smem[];
    __half (*As)[128][40] = (__half(*)[128][40])smem;
    __half (*Bs)[32][136] = (__half(*)[32][136])(smem + 3 * AS_H);

    int row0 = blockIdx.y * 128;
    int col0 = blockIdx.x * 128;
    int tid  = threadIdx.x;
    int w    = tid >> 5;
    int lane = tid & 31;
    int qid  = lane >> 2;
    int tq   = lane & 3;
    int m0w  = (w >> 1) * 64;
    int n0w  = (w & 1) * 64;

    float acc[4][8][4];
#pragma unroll
    for (int i = 0; i < 4; i++)
#pragma unroll
        for (int jj = 0; jj < 8; jj++)
#pragma unroll
            for (int q = 0; q < 4; q++) acc[i][jj][q] = 0.f;

    const int NC = K / 32;

    auto load_stage = [&](int kc, int s) {
        int k0 = kc * 32;
#pragma unroll
        for (int i = 0; i < 4; i++) {          // A: 128 rows x 32 halves = 512 segs
            int seg = tid + i * 128;
            int row = seg >> 2;
            int c8  = (seg & 3) * 8;
            int gr  = row0 + row;
            const __half* srcp = &A[(size_t)(gr < n ? gr : 0) * K + k0 + c8];
            cp16p(&As[s][row][c8], srcp, gr < n ? 16 : 0);
        }
#pragma unroll
        for (int i = 0; i < 4; i++) {          // B: 32 rows x 128 halves = 512 segs
            int seg = tid + i * 128;
            int row = seg >> 4;
            int c8  = (seg & 15) * 8;
            cp16(&Bs[s][row][c8], &B[(size_t)(k0 + row) * 256 + col0 + c8]);
        }
        CP_COMMIT();
    };

    load_stage(0, 0);
    if (NC > 1) load_stage(1, 1);

    for (int kc = 0; kc < NC; kc++) {
        if (kc + 1 < NC) asm volatile("cp.async.wait_group 1;" ::: "memory");
        else             asm volatile("cp.async.wait_group 0;" ::: "memory");
        __syncthreads();
        if (kc + 2 < NC) load_stage(kc + 2, (kc + 2) % 3);

        int s = kc % 3;
#pragma unroll
        for (int kk = 0; kk < 32; kk += 16) {
            uint32_t a[4][4], b[8][2];
#pragma unroll
            for (int mb = 0; mb < 4; mb++) {
                int r0 = m0w + mb * 16 + qid;
                a[mb][0] = *(const uint32_t*)&As[s][r0][kk + 2 * tq];
                a[mb][1] = *(const uint32_t*)&As[s][r0 + 8][kk + 2 * tq];
                a[mb][2] = *(const uint32_t*)&As[s][r0][kk + 2 * tq + 8];
                a[mb][3] = *(const uint32_t*)&As[s][r0 + 8][kk + 2 * tq + 8];
            }
#pragma unroll
            for (int nb = 0; nb < 8; nb++) {
                int c = n0w + nb * 8 + qid;
                __half2 b0 = __halves2half2(Bs[s][kk + 2 * tq][c],
                                            Bs[s][kk + 2 * tq + 1][c]);
                __half2 b1 = __halves2half2(Bs[s][kk + 2 * tq + 8][c],
                                            Bs[s][kk + 2 * tq + 9][c]);
                b[nb][0] = *(uint32_t*)&b0;
                b[nb][1] = *(uint32_t*)&b1;
            }
#pragma unroll
            for (int mb = 0; mb < 4; mb++)
#pragma unroll
                for (int nb = 0; nb < 8; nb++)
                    mma16(acc[mb][nb], a[mb], b[nb]);
        }
        __syncthreads();
    }

    // epilogue: rescale (x2^8), bias, ReLU, (+ residual) / stores
#pragma unroll
    for (int mb = 0; mb < 4; mb++) {
        int r0g = row0 + m0w + mb * 16 + qid;
        int r1g = r0g + 8;
#pragma unroll
        for (int nb = 0; nb < 8; nb++) {
            int cg = col0 + n0w + nb * 8 + tq * 2;
            float bs0 = bias[cg], bs1 = bias[cg + 1];
            float v0 = fmaxf(acc[mb][nb][0] * H_UNSCALE + bs0, 0.f);
            float v1 = fmaxf(acc[mb][nb][1] * H_UNSCALE + bs1, 0.f);
            float v2 = fmaxf(acc[mb][nb][2] * H_UNSCALE + bs0, 0.f);
            float v3 = fmaxf(acc[mb][nb][3] * H_UNSCALE + bs1, 0.f);
            if (HALFOUT) {
                if (r0g < n) {
                    __half2 o = __floats2half2_rn(v0 * H_SCALE, v1 * H_SCALE);
                    *(__half2*)&CH[(size_t)r0g * 256 + cg] = o;
                }
                if (r1g < n) {
                    __half2 o = __floats2half2_rn(v2 * H_SCALE, v3 * H_SCALE);
                    *(__half2*)&CH[(size_t)r1g * 256 + cg] = o;
                }
            } else {
                if (r0g < n) {
                    if (RESID) {
                        v0 += R[(size_t)r0g * 256 + cg];
                        v1 += R[(size_t)r0g * 256 + cg + 1];
                    }
                    C[(size_t)r0g * 256 + cg]     = v0;
                    C[(size_t)r0g * 256 + cg + 1] = v1;
                    if (CH) {
                        __half2 o = __floats2half2_rn(v0 * H_SCALE, v1 * H_SCALE);
                        *(__half2*)&CH[(size_t)r0g * 256 + cg] = o;
                    }
                }
                if (r1g < n) {
                    if (RESID) {
                        v2 += R[(size_t)r1g * 256 + cg];
                        v3 += R[(size_t)r1g * 256 + cg + 1];
                    }
                    C[(size_t)r1g * 256 + cg]     = v2;
                    C[(size_t)r1g * 256 + cg + 1] = v3;
                    if (CH) {
                        __half2 o = __floats2half2_rn(v2 * H_SCALE, v3 * H_SCALE);
                        *(__half2*)&CH[(size_t)r1g * 256 + cg] = o;
                    }
                }
            }
        }
    }
}

// ---------------------------------------------------------------------------
// Pooling (unchanged)
// ---------------------------------------------------------------------------
__global__ void k_pool(const float* __restrict__ h, const int* __restrict__ batch) {
    __shared__ int sb[128];
    int i0 = blockIdx.x * 128;
    int d = threadIdx.x;
    int end = N_NODES - i0;
    if (end > 128) end = 128;
    if (d < 128 && d < end) sb[d] = batch[i0 + d];
    __syncthreads();
    int cur = sb[0];
    float acc = 0.f;
    for (int t = 0; t < end; t++) {
        int b = sb[t];
        if (b != cur) {
            atomicAdd(&g_pooled[cur * HIDDEN + d], acc);
            acc = 0.f;
            cur = b;
        }
        acc += h[(size_t)(i0 + t) * HIDDEN + d];
    }
    atomicAdd(&g_pooled[cur * HIDDEN + d], acc);
    if (d == 0) {
        int c = 0, cb = sb[0];
        for (int t = 0; t < end; t++) {
            if (sb[t] != cb) {
                atomicAdd(&g_cnt[cb], (float)c);
                c = 0;
                cb = sb[t];
            }
            c++;
        }
        atomicAdd(&g_cnt[cb], (float)c);
    }
}

// ---------------------------------------------------------------------------
// Head (unchanged)
// ---------------------------------------------------------------------------
__global__ void k_head(const float* __restrict__ g,
                       const float* __restrict__ hW1, const float* __restrict__ hb1,
                       const float* __restrict__ hW2, const float* __restrict__ hb2,
                       float* __restrict__ out) {
    __shared__ float feat[HIDDEN + GLOB_DIM];
    __shared__ float red[256];
    int gi = blockIdx.x;
    int t = threadIdx.x;
    float cnt = fmaxf(g_cnt[gi], 1.0f);
    feat[t] = g_pooled[gi * HIDDEN + t] / cnt;
    if (t < GLOB_DIM) feat[HIDDEN + t] = g[gi * GLOB_DIM + t];
    __syncthreads();
    float acc = hb1[t];
    for (int k = 0; k < HIDDEN + GLOB_DIM; k++)
        acc += feat[k] * hW1[k * HIDDEN + t];
    acc = fmaxf(acc, 0.f) * hW2[t];
    red[t] = acc;
    __syncthreads();
    for (int off = 128; off > 0; off >>= 1) {
        if (t < off) red[t] += red[t + off];
        __syncthreads();
    }
    if (t == 0) out[gi] = red[0] + hb2[0];
}

// ---------------------------------------------------------------------------
// kernel_launch
// ---------------------------------------------------------------------------
extern "C" void kernel_launch(void* const* d_in, const int* in_sizes, int n_in,
                              void* d_out, int out_size) {
    const float* x     = (const float*)d_in[0];
    const int*   ei    = (const int*)  d_in[1];
    const int*   batch = (const int*)  d_in[2];
    const float* g     = (const float*)d_in[3];
    const float* W1[NUM_LAYERS], *b1[NUM_LAYERS], *W2[NUM_LAYERS], *b2[NUM_LAYERS];
    for (int l = 0; l < NUM_LAYERS; l++) {
        W1[l] = (const float*)d_in[4 + 4 * l + 0];
        b1[l] = (const float*)d_in[4 + 4 * l + 1];
        W2[l] = (const float*)d_in[4 + 4 * l + 2];
        b2[l] = (const float*)d_in[4 + 4 * l + 3];
    }
    const float* eps = (const float*)d_in[20];
    const float* hW1 = (const float*)d_in[21];
    const float* hb1 = (const float*)d_in[22];
    const float* hW2 = (const float*)d_in[23];
    const float* hb2 = (const float*)d_in[24];
    float* out = (float*)d_out;

    const int* src = ei;
    const int* dst = ei + N_EDGES;

    float  *hA, *hB;
    __half *hh, *z, *t, *wh;
    cudaGetSymbolAddress((void**)&hA, g_hA);
    cudaGetSymbolAddress((void**)&hB, g_hB);
    cudaGetSymbolAddress((void**)&hh, g_hh);
    cudaGetSymbolAddress((void**)&z,  g_z);
    cudaGetSymbolAddress((void**)&t,  g_t);
    cudaGetSymbolAddress((void**)&wh, g_Wh);

    cudaFuncSetAttribute(k_gemm<128, false, true >, cudaFuncAttributeMaxDynamicSharedMemorySize, GEMM_SMEM_BYTES);
    cudaFuncSetAttribute(k_gemm<256, false, true >, cudaFuncAttributeMaxDynamicSharedMemorySize, GEMM_SMEM_BYTES);
    cudaFuncSetAttribute(k_gemm<256, false, false>, cudaFuncAttributeMaxDynamicSharedMemorySize, GEMM_SMEM_BYTES);
    cudaFuncSetAttribute(k_gemm<256, true,  false>, cudaFuncAttributeMaxDynamicSharedMemorySize, GEMM_SMEM_BYTES);

    // CSR build
    k_zero <<<(N_NODES + 255) / 256, 256>>>();
    k_count<<<(N_EDGES / 4 + 255) / 256, 256>>>(dst);
    k_scan <<<1, 512>>>();
    k_fill <<<(N_EDGES / 4 + 255) / 256, 256>>>(src, dst);

    // Round all weights to half (natural [K][256] layout)
    {
        P8 ps;
        for (int l = 0; l < NUM_LAYERS; l++) {
            ps.p[2 * l]     = W1[l];
            ps.n[2 * l]     = ((l == 0) ? NODE_DIM : HIDDEN) * HIDDEN;
            ps.p[2 * l + 1] = W2[l];
            ps.n[2 * l + 1] = HIDDEN * HIDDEN;
        }
        k_round_all<<<(8 * 65536) / 256, 256>>>(ps, wh);
    }

    dim3 ggrid(2, (N_NODES + 127) / 128);

    const float* h_in = x;
    float* h_out = hA;
    for (int l = 0; l < NUM_LAYERS; l++) {
        __half* wh1 = wh + (size_t)(2 * l)     * 65536;
        __half* wh2 = wh + (size_t)(2 * l + 1) * 65536;
        __half* mirror = (l < NUM_LAYERS - 1) ? hh : nullptr;
        if (l == 0) {
            k_aggr<NODE_DIM / 4><<<(N_NODES + 3) / 4, 128>>>(h_in, z, eps, l);
            k_gemm<128, false, true ><<<ggrid, 128, GEMM_SMEM_BYTES>>>(z, wh1, b1[l], nullptr, nullptr, t, N_NODES);
            k_gemm<256, false, false><<<ggrid, 128, GEMM_SMEM_BYTES>>>(t, wh2, b2[l], nullptr, h_out, mirror, N_NODES);
        } else {
            k_aggr_h<HIDDEN / 8><<<(N_NODES + 3) / 4, 128>>>(hh, z, eps, l);
            k_gemm<256, false, true ><<<ggrid, 128, GEMM_SMEM_BYTES>>>(z, wh1, b1[l], nullptr, nullptr, t, N_NODES);
            k_gemm<256, true,  false><<<ggrid, 128, GEMM_SMEM_BYTES>>>(t, wh2, b2[l], h_in, h_out, mirror, N_NODES);
        }
        h_in = h_out;
        h_out = (h_out == hA) ? hB : hA;
    }

    k_pool<<<(N_NODES + 127) / 128, 256>>>(h_in, batch);
    k_head<<<N_GRAPHS, 256>>>(g, hW1, hb1, hW2, hb2, out);
}

// round 13
// speedup vs baseline: 1.1502x; 1.1502x over previous
#include <cuda_runtime.h>
#include <cuda_fp16.h>
#include <cstdint>
#include <cstddef>

// Problem constants
#define N_NODES   20000
#define N_EDGES   320000
#define N_GRAPHS  64
#define NODE_DIM  128
#define GLOB_DIM  16
#define HIDDEN    256
#define NUM_LAYERS 4

// Dynamic-range shift for fp16 storage of z/t (exact power of two)
#define H_SCALE   (1.0f / 256.0f)
#define H_UNSCALE 256.0f

// ---------------------------------------------------------------------------
// Scratch (static __device__ allocations)
// ---------------------------------------------------------------------------
__device__ float  g_hA[N_NODES * HIDDEN];
__device__ float  g_hB[N_NODES * HIDDEN];
__device__ __half g_z [N_NODES * HIDDEN];     // aggregated features (half, x2^-8)
__device__ __half g_t [N_NODES * HIDDEN];     // MLP hidden (half, x2^-8)
__device__ __half g_Wt[8 * HIDDEN * HIDDEN];  // half weights, TRANSPOSED [n][k] layout

__device__ int    g_deg   [N_NODES];
__device__ int    g_rowptr[N_NODES + 1];
__device__ int    g_cursor[N_NODES];
__device__ int    g_col   [N_EDGES];

__device__ float  g_pooled[N_GRAPHS * HIDDEN];
__device__ float  g_cnt   [N_GRAPHS];

// ---------------------------------------------------------------------------
// Helpers
// ---------------------------------------------------------------------------
__device__ __forceinline__ void mma16(float* c, const uint32_t* a, const uint32_t* b) {
    asm volatile(
        "mma.sync.aligned.m16n8k16.row.col.f32.f16.f16.f32 "
        "{%0,%1,%2,%3}, {%4,%5,%6,%7}, {%8,%9}, {%0,%1,%2,%3};"
        : "+f"(c[0]), "+f"(c[1]), "+f"(c[2]), "+f"(c[3])
        : "r"(a[0]), "r"(a[1]), "r"(a[2]), "r"(a[3]), "r"(b[0]), "r"(b[1]));
}

__device__ __forceinline__ void cp16p(void* dst, const void* src, int srcbytes) {
    uint32_t d = (uint32_t)__cvta_generic_to_shared(dst);
    asm volatile("cp.async.cg.shared.global [%0], [%1], 16, %2;"
                 :: "r"(d), "l"(src), "r"(srcbytes));
}
__device__ __forceinline__ void cp16(void* dst, const void* src) {
    uint32_t d = (uint32_t)__cvta_generic_to_shared(dst);
    asm volatile("cp.async.cg.shared.global [%0], [%1], 16;"
                 :: "r"(d), "l"(src));
}
#define CP_COMMIT() asm volatile("cp.async.commit_group;" ::: "memory")

// ---------------------------------------------------------------------------
// CSR build (unchanged)
// ---------------------------------------------------------------------------
__global__ void k_zero() {
    int i = blockIdx.x * blockDim.x + threadIdx.x;
    if (i < N_NODES) g_deg[i] = 0;
    if (i < N_GRAPHS * HIDDEN) g_pooled[i] = 0.f;
    if (i < N_GRAPHS) g_cnt[i] = 0.f;
}

__global__ void k_count(const int* __restrict__ dst) {
    int e = (blockIdx.x * blockDim.x + threadIdx.x) * 4;
#pragma unroll
    for (int j = 0; j < 4; j++)
        if (e + j < N_EDGES) atomicAdd(&g_deg[dst[e + j]], 1);
}

__global__ void k_scan() {
    const int T = 512;
    const int CH = (N_NODES + T - 1) / T;
    __shared__ int part[T];
    int t = threadIdx.x;
    int base = t * CH;
    int s = 0;
    for (int j = 0; j < CH; j++) {
        int i = base + j;
        if (i < N_NODES) s += g_deg[i];
    }
    part[t] = s;
    __syncthreads();
    for (int off = 1; off < T; off <<= 1) {
        int v = (t >= off) ? part[t - off] : 0;
        __syncthreads();
        part[t] += v;
        __syncthreads();
    }
    int run = (t > 0) ? part[t - 1] : 0;
    for (int j = 0; j < CH; j++) {
        int i = base + j;
        if (i < N_NODES) {
            g_rowptr[i] = run;
            g_cursor[i] = run;
            run += g_deg[i];
        }
    }
    if (t == T - 1) g_rowptr[N_NODES] = run;
}

__global__ void k_fill(const int* __restrict__ src, const int* __restrict__ dst) {
    int e = (blockIdx.x * blockDim.x + threadIdx.x) * 4;
#pragma unroll
    for (int j = 0; j < 4; j++) {
        if (e + j < N_EDGES) {
            int d = dst[e + j];
            int p = atomicAdd(&g_cursor[d], 1);
            g_col[p] = src[e + j];
        }
    }
}

// ---------------------------------------------------------------------------
// Weight prep: round to half AND transpose -> Wt[slot][n][k]
// ---------------------------------------------------------------------------
struct P8 { const float* p[8]; int n[8]; };

__global__ void k_prep(P8 ps, __half* __restrict__ out) {
    int i = blockIdx.x * blockDim.x + threadIdx.x;
    int slot = i >> 16;
    int off  = i & 65535;
    if (slot >= 8 || off >= ps.n[slot]) return;
    int K  = ps.n[slot] >> 8;     // 128 or 256
    int k  = off >> 8;            // coalesced read: off = k*256 + nn
    int nn = off & 255;
    out[(size_t)slot * 65536 + (size_t)nn * K + k] = __float2half_rn(ps.p[slot][off]);
}

// ---------------------------------------------------------------------------
// GIN aggregation — fp32 gather/accumulate; store half scaled by 2^-8
// (byte-identical to R10)
// ---------------------------------------------------------------------------
template <int DIM4>
__global__ void k_aggr(const float* __restrict__ h, __half* __restrict__ z,
                       const float* __restrict__ eps, int layer) {
    const int NPB = 128 / DIM4;
    int v = blockIdx.x * NPB + threadIdx.x / DIM4;
    if (v >= N_NODES) return;
    int t = threadIdx.x % DIM4;
    float ep = 1.0f + eps[layer];
    const float4* h4 = (const float4*)h;
    float4 a = h4[(size_t)v * DIM4 + t];
    float4 acc;
    acc.x = ep * a.x; acc.y = ep * a.y; acc.z = ep * a.z; acc.w = ep * a.w;
    int j = g_rowptr[v], s1 = g_rowptr[v + 1];
    for (; j + 4 <= s1; j += 4) {
        int i0 = g_col[j], i1 = g_col[j + 1], i2 = g_col[j + 2], i3 = g_col[j + 3];
        float4 b0 = h4[(size_t)i0 * DIM4 + t];
        float4 b1 = h4[(size_t)i1 * DIM4 + t];
        float4 b2 = h4[(size_t)i2 * DIM4 + t];
        float4 b3 = h4[(size_t)i3 * DIM4 + t];
        acc.x += (b0.x + b1.x) + (b2.x + b3.x);
        acc.y += (b0.y + b1.y) + (b2.y + b3.y);
        acc.z += (b0.z + b1.z) + (b2.z + b3.z);
        acc.w += (b0.w + b1.w) + (b2.w + b3.w);
    }
    for (; j < s1; ++j) {
        int s = g_col[j];
        float4 b = h4[(size_t)s * DIM4 + t];
        acc.x += b.x; acc.y += b.y; acc.z += b.z; acc.w += b.w;
    }
    __half2 o0 = __floats2half2_rn(acc.x * H_SCALE, acc.y * H_SCALE);
    __half2 o1 = __floats2half2_rn(acc.z * H_SCALE, acc.w * H_SCALE);
    uint2 st;
    st.x = *(uint32_t*)&o0;
    st.y = *(uint32_t*)&o1;
    ((uint2*)z)[(size_t)v * DIM4 + t] = st;
}

// ---------------------------------------------------------------------------
// fp16 tensor-core GEMM: C[n x 256] = epi((A*2^-8)[n x K] @ Wt^T)
// A: half [n][K].  Wt: half [256][K] (pre-transposed -> B tile layout == A).
// 128 threads (4 warps), CTA tile 128x128, warp tile 64x64, BK=32,
// 3-stage cp.async ring, 2 CTAs/SM.
// ---------------------------------------------------------------------------
static constexpr int AS_H = 128 * 40;   // halves per A stage ([m][k], pitch 40)
static constexpr int BS_H = 128 * 40;   // halves per B stage ([n][k], pitch 40)
static constexpr int GEMM_SMEM_BYTES = 3 * (AS_H + BS_H) * 2;   // 61440

template <int K, bool RESID, bool HALFOUT>
__global__ __launch_bounds__(128, 2)
void k_gemm(const __half* __restrict__ A, const __half* __restrict__ Bt,
            const float* __restrict__ bias, const float* __restrict__ R,
            float* __restrict__ C, __half* __restrict__ CH, int n) {
    extern __shared__ __half smem[];
    __half (*As)[128][40] = (__half(*)[128][40])smem;
    __half (*Bs)[128][40] = (__half(*)[128][40])(smem + 3 * AS_H);

    int row0 = blockIdx.y * 128;
    int col0 = blockIdx.x * 128;
    int tid  = threadIdx.x;
    int w    = tid >> 5;
    int lane = tid & 31;
    int qid  = lane >> 2;
    int tq   = lane & 3;
    int m0w  = (w >> 1) * 64;
    int n0w  = (w & 1) * 64;

    float acc[4][8][4];
#pragma unroll
    for (int i = 0; i < 4; i++)
#pragma unroll
        for (int jj = 0; jj < 8; jj++)
#pragma unroll
            for (int q = 0; q < 4; q++) acc[i][jj][q] = 0.f;

    const int NC = K / 32;

    auto load_stage = [&](int kc, int s) {
        int k0 = kc * 32;
#pragma unroll
        for (int i = 0; i < 4; i++) {          // A: 128 rows x 32 halves = 512 segs
            int seg = tid + i * 128;
            int row = seg >> 2;
            int c8  = (seg & 3) * 8;
            int gr  = row0 + row;
            const __half* srcp = &A[(size_t)(gr < n ? gr : 0) * K + k0 + c8];
            cp16p(&As[s][row][c8], srcp, gr < n ? 16 : 0);
        }
#pragma unroll
        for (int i = 0; i < 4; i++) {          // B: 128 cols x 32 halves = 512 segs
            int seg = tid + i * 128;
            int row = seg >> 2;
            int c8  = (seg & 3) * 8;
            cp16(&Bs[s][row][c8], &Bt[(size_t)(col0 + row) * K + k0 + c8]);
        }
        CP_COMMIT();
    };

    load_stage(0, 0);
    if (NC > 1) load_stage(1, 1);

    for (int kc = 0; kc < NC; kc++) {
        if (kc + 1 < NC) asm volatile("cp.async.wait_group 1;" ::: "memory");
        else             asm volatile("cp.async.wait_group 0;" ::: "memory");
        __syncthreads();
        if (kc + 2 < NC) load_stage(kc + 2, (kc + 2) % 3);

        int s = kc % 3;
#pragma unroll
        for (int kk = 0; kk < 32; kk += 16) {
            uint32_t a[4][4], b[8][2];
#pragma unroll
            for (int mb = 0; mb < 4; mb++) {
                int r0 = m0w + mb * 16 + qid;
                a[mb][0] = *(const uint32_t*)&As[s][r0][kk + 2 * tq];
                a[mb][1] = *(const uint32_t*)&As[s][r0 + 8][kk + 2 * tq];
                a[mb][2] = *(const uint32_t*)&As[s][r0][kk + 2 * tq + 8];
                a[mb][3] = *(const uint32_t*)&As[s][r0 + 8][kk + 2 * tq + 8];
            }
#pragma unroll
            for (int nb = 0; nb < 8; nb++) {
                int c = n0w + nb * 8 + qid;
                b[nb][0] = *(const uint32_t*)&Bs[s][c][kk + 2 * tq];
                b[nb][1] = *(const uint32_t*)&Bs[s][c][kk + 2 * tq + 8];
            }
#pragma unroll
            for (int mb = 0; mb < 4; mb++)
#pragma unroll
                for (int nb = 0; nb < 8; nb++)
                    mma16(acc[mb][nb], a[mb], b[nb]);
        }
        __syncthreads();
    }

    // epilogue: rescale (x2^8), bias, ReLU, (+ residual) / half store (x2^-8)
#pragma unroll
    for (int mb = 0; mb < 4; mb++) {
        int r0g = row0 + m0w + mb * 16 + qid;
        int r1g = r0g + 8;
#pragma unroll
        for (int nb = 0; nb < 8; nb++) {
            int cg = col0 + n0w + nb * 8 + tq * 2;
            float bs0 = bias[cg], bs1 = bias[cg + 1];
            float v0 = fmaxf(acc[mb][nb][0] * H_UNSCALE + bs0, 0.f);
            float v1 = fmaxf(acc[mb][nb][1] * H_UNSCALE + bs1, 0.f);
            float v2 = fmaxf(acc[mb][nb][2] * H_UNSCALE + bs0, 0.f);
            float v3 = fmaxf(acc[mb][nb][3] * H_UNSCALE + bs1, 0.f);
            if (HALFOUT) {
                if (r0g < n) {
                    __half2 o = __floats2half2_rn(v0 * H_SCALE, v1 * H_SCALE);
                    *(__half2*)&CH[(size_t)r0g * 256 + cg] = o;
                }
                if (r1g < n) {
                    __half2 o = __floats2half2_rn(v2 * H_SCALE, v3 * H_SCALE);
                    *(__half2*)&CH[(size_t)r1g * 256 + cg] = o;
                }
            } else {
                if (r0g < n) {
                    if (RESID) {
                        v0 += R[(size_t)r0g * 256 + cg];
                        v1 += R[(size_t)r0g * 256 + cg + 1];
                    }
                    C[(size_t)r0g * 256 + cg]     = v0;
                    C[(size_t)r0g * 256 + cg + 1] = v1;
                }
                if (r1g < n) {
                    if (RESID) {
                        v2 += R[(size_t)r1g * 256 + cg];
                        v3 += R[(size_t)r1g * 256 + cg + 1];
                    }
                    C[(size_t)r1g * 256 + cg]     = v2;
                    C[(size_t)r1g * 256 + cg + 1] = v3;
                }
            }
        }
    }
}

// ---------------------------------------------------------------------------
// Pooling (unchanged)
// ---------------------------------------------------------------------------
__global__ void k_pool(const float* __restrict__ h, const int* __restrict__ batch) {
    __shared__ int sb[128];
    int i0 = blockIdx.x * 128;
    int d = threadIdx.x;
    int end = N_NODES - i0;
    if (end > 128) end = 128;
    if (d < 128 && d < end) sb[d] = batch[i0 + d];
    __syncthreads();
    int cur = sb[0];
    float acc = 0.f;
    for (int t = 0; t < end; t++) {
        int b = sb[t];
        if (b != cur) {
            atomicAdd(&g_pooled[cur * HIDDEN + d], acc);
            acc = 0.f;
            cur = b;
        }
        acc += h[(size_t)(i0 + t) * HIDDEN + d];
    }
    atomicAdd(&g_pooled[cur * HIDDEN + d], acc);
    if (d == 0) {
        int c = 0, cb = sb[0];
        for (int t = 0; t < end; t++) {
            if (sb[t] != cb) {
                atomicAdd(&g_cnt[cb], (float)c);
                c = 0;
                cb = sb[t];
            }
            c++;
        }
        atomicAdd(&g_cnt[cb], (float)c);
    }
}

// ---------------------------------------------------------------------------
// Head (unchanged)
// ---------------------------------------------------------------------------
__global__ void k_head(const float* __restrict__ g,
                       const float* __restrict__ hW1, const float* __restrict__ hb1,
                       const float* __restrict__ hW2, const float* __restrict__ hb2,
                       float* __restrict__ out) {
    __shared__ float feat[HIDDEN + GLOB_DIM];
    __shared__ float red[256];
    int gi = blockIdx.x;
    int t = threadIdx.x;
    float cnt = fmaxf(g_cnt[gi], 1.0f);
    feat[t] = g_pooled[gi * HIDDEN + t] / cnt;
    if (t < GLOB_DIM) feat[HIDDEN + t] = g[gi * GLOB_DIM + t];
    __syncthreads();
    float acc = hb1[t];
    for (int k = 0; k < HIDDEN + GLOB_DIM; k++)
        acc += feat[k] * hW1[k * HIDDEN + t];
    acc = fmaxf(acc, 0.f) * hW2[t];
    red[t] = acc;
    __syncthreads();
    for (int off = 128; off > 0; off >>= 1) {
        if (t < off) red[t] += red[t + off];
        __syncthreads();
    }
    if (t == 0) out[gi] = red[0] + hb2[0];
}

// ---------------------------------------------------------------------------
// kernel_launch
// ---------------------------------------------------------------------------
extern "C" void kernel_launch(void* const* d_in, const int* in_sizes, int n_in,
                              void* d_out, int out_size) {
    const float* x     = (const float*)d_in[0];
    const int*   ei    = (const int*)  d_in[1];
    const int*   batch = (const int*)  d_in[2];
    const float* g     = (const float*)d_in[3];
    const float* W1[NUM_LAYERS], *b1[NUM_LAYERS], *W2[NUM_LAYERS], *b2[NUM_LAYERS];
    for (int l = 0; l < NUM_LAYERS; l++) {
        W1[l] = (const float*)d_in[4 + 4 * l + 0];
        b1[l] = (const float*)d_in[4 + 4 * l + 1];
        W2[l] = (const float*)d_in[4 + 4 * l + 2];
        b2[l] = (const float*)d_in[4 + 4 * l + 3];
    }
    const float* eps = (const float*)d_in[20];
    const float* hW1 = (const float*)d_in[21];
    const float* hb1 = (const float*)d_in[22];
    const float* hW2 = (const float*)d_in[23];
    const float* hb2 = (const float*)d_in[24];
    float* out = (float*)d_out;

    const int* src = ei;
    const int* dst = ei + N_EDGES;

    float  *hA, *hB;
    __half *z, *t, *wt;
    cudaGetSymbolAddress((void**)&hA, g_hA);
    cudaGetSymbolAddress((void**)&hB, g_hB);
    cudaGetSymbolAddress((void**)&z,  g_z);
    cudaGetSymbolAddress((void**)&t,  g_t);
    cudaGetSymbolAddress((void**)&wt, g_Wt);

    cudaFuncSetAttribute(k_gemm<128, false, true >, cudaFuncAttributeMaxDynamicSharedMemorySize, GEMM_SMEM_BYTES);
    cudaFuncSetAttribute(k_gemm<256, false, true >, cudaFuncAttributeMaxDynamicSharedMemorySize, GEMM_SMEM_BYTES);
    cudaFuncSetAttribute(k_gemm<256, false, false>, cudaFuncAttributeMaxDynamicSharedMemorySize, GEMM_SMEM_BYTES);
    cudaFuncSetAttribute(k_gemm<256, true,  false>, cudaFuncAttributeMaxDynamicSharedMemorySize, GEMM_SMEM_BYTES);

    // CSR build
    k_zero <<<(N_NODES + 255) / 256, 256>>>();
    k_count<<<(N_EDGES / 4 + 255) / 256, 256>>>(dst);
    k_scan <<<1, 512>>>();
    k_fill <<<(N_EDGES / 4 + 255) / 256, 256>>>(src, dst);

    // Round all weights to half + transpose to [n][k]
    {
        P8 ps;
        for (int l = 0; l < NUM_LAYERS; l++) {
            ps.p[2 * l]     = W1[l];
            ps.n[2 * l]     = ((l == 0) ? NODE_DIM : HIDDEN) * HIDDEN;
            ps.p[2 * l + 1] = W2[l];
            ps.n[2 * l + 1] = HIDDEN * HIDDEN;
        }
        k_prep<<<(8 * 65536) / 256, 256>>>(ps, wt);
    }

    dim3 ggrid(2, (N_NODES + 127) / 128);

    const float* h_in = x;
    float* h_out = hA;
    for (int l = 0; l < NUM_LAYERS; l++) {
        __half* wt1 = wt + (size_t)(2 * l)     * 65536;
        __half* wt2 = wt + (size_t)(2 * l + 1) * 65536;
        if (l == 0) {
            k_aggr<NODE_DIM / 4><<<(N_NODES + 3) / 4, 128>>>(h_in, z, eps, l);
            k_gemm<128, false, true ><<<ggrid, 128, GEMM_SMEM_BYTES>>>(z, wt1, b1[l], nullptr, nullptr, t, N_NODES);
            k_gemm<256, false, false><<<ggrid, 128, GEMM_SMEM_BYTES>>>(t, wt2, b2[l], nullptr, h_out, nullptr, N_NODES);
        } else {
            k_aggr<HIDDEN / 4><<<(N_NODES + 1) / 2, 128>>>(h_in, z, eps, l);
            k_gemm<256, false, true ><<<ggrid, 128, GEMM_SMEM_BYTES>>>(z, wt1, b1[l], nullptr, nullptr, t, N_NODES);
            k_gemm<256, true,  false><<<ggrid, 128, GEMM_SMEM_BYTES>>>(t, wt2, b2[l], h_in, h_out, nullptr, N_NODES);
        }
        h_in = h_out;
        h_out = (h_out == hA) ? hB : hA;
    }

    k_pool<<<(N_NODES + 127) / 128, 256>>>(h_in, batch);
    k_head<<<N_GRAPHS, 256>>>(g, hW1, hb1, hW2, hb2, out);
}